// round 3
// baseline (speedup 1.0000x reference)
#include <cuda_runtime.h>
#include <math.h>

// Problem dims
#define TSLICES 10
#define NTOPICS 50
#define M_ROWS  (TSLICES * NTOPICS)   // 500
#define N_COLS  50000
#define K_DIM   1024
#define BATCH   256

// ---------------------------------------------------------------------------
// Scratch (device globals — no runtime allocation allowed)
// ---------------------------------------------------------------------------
__device__ float g_logits[(size_t)M_ROWS * N_COLS];  // 100 MB
__device__ float g_rowmax[M_ROWS];
__device__ float g_rowsum[M_ROWS];
__device__ float g_c[BATCH * NTOPICS];               // theta[b,k]/S[t_b,k]
__device__ int   g_tidx[BATCH];

// ---------------------------------------------------------------------------
// k0: normalize time_index. The reference requests int64 but JAX without x64
// silently produces int32 — detect at runtime. For int64 little-endian data
// with values in [0,10), every odd 32-bit word is 0. Only words [0,256) are
// read for detection (valid under both layouts).
// ---------------------------------------------------------------------------
__global__ void k0_index(const int* __restrict__ tix_words) {
    __shared__ int s_nonzero;
    int t = threadIdx.x;                  // 256 threads
    if (t == 0) s_nonzero = 0;
    __syncthreads();
    if ((t & 1) && tix_words[t] != 0) atomicOr(&s_nonzero, 1);
    __syncthreads();
    bool is64 = (s_nonzero == 0);
    g_tidx[t] = is64 ? tix_words[2 * t] : tix_words[t];
}

// ---------------------------------------------------------------------------
// k1: logits SGEMM.  L[r, v] = A[r,:] . B[v,:]   (both K-contiguous, NT form)
//   A = topic_embeddings reshaped (500, 1024), B = word_embeddings (50000,1024)
// 128x128 CTA tile, BK=16, 256 threads, 8x8 per-thread micro-tile, fp32.
// ---------------------------------------------------------------------------
#define BM 128
#define BN 128
#define BK 16
#define TM 8
#define TN 8

__global__ __launch_bounds__(256, 2)
void k1_gemm(const float* __restrict__ A, const float* __restrict__ B) {
    __shared__ float sA[BK][BM];
    __shared__ float sB[BK][BN];

    const int tid = threadIdx.x;
    const int tx  = tid & 15;         // 0..15  -> column group
    const int ty  = tid >> 4;         // 0..15  -> row group
    const int rowBase = blockIdx.y * BM;
    const int colBase = blockIdx.x * BN;

    // loader mapping: each thread loads 2 float4 per operand per k-chunk
    const int ldRow = tid >> 2;        // 0..63
    const int ldK   = (tid & 3) * 4;   // 0,4,8,12

    float acc[TM][TN];
    #pragma unroll
    for (int i = 0; i < TM; i++)
        #pragma unroll
        for (int j = 0; j < TN; j++) acc[i][j] = 0.0f;

    for (int k0 = 0; k0 < K_DIM; k0 += BK) {
        #pragma unroll
        for (int h = 0; h < 2; h++) {
            const int rr = ldRow + h * 64;
            // A tile
            int gr = rowBase + rr;
            float4 va = make_float4(0.f, 0.f, 0.f, 0.f);
            if (gr < M_ROWS)
                va = *(const float4*)(A + (size_t)gr * K_DIM + k0 + ldK);
            sA[ldK + 0][rr] = va.x;
            sA[ldK + 1][rr] = va.y;
            sA[ldK + 2][rr] = va.z;
            sA[ldK + 3][rr] = va.w;
            // B tile
            int gc = colBase + rr;
            float4 vb = make_float4(0.f, 0.f, 0.f, 0.f);
            if (gc < N_COLS)
                vb = *(const float4*)(B + (size_t)gc * K_DIM + k0 + ldK);
            sB[ldK + 0][rr] = vb.x;
            sB[ldK + 1][rr] = vb.y;
            sB[ldK + 2][rr] = vb.z;
            sB[ldK + 3][rr] = vb.w;
        }
        __syncthreads();

        #pragma unroll
        for (int kk = 0; kk < BK; kk++) {
            float ra[TM], rb[TN];
            #pragma unroll
            for (int i = 0; i < TM; i++) ra[i] = sA[kk][ty * TM + i];
            #pragma unroll
            for (int j = 0; j < TN; j++) rb[j] = sB[kk][tx * TN + j];
            #pragma unroll
            for (int i = 0; i < TM; i++)
                #pragma unroll
                for (int j = 0; j < TN; j++)
                    acc[i][j] += ra[i] * rb[j];
        }
        __syncthreads();
    }

    // Store (row/col guarded; vectorize when the 8-col strip is fully in-range)
    const int vBase = colBase + tx * TN;
    const bool fullCols = (vBase + TN) <= N_COLS;
    #pragma unroll
    for (int i = 0; i < TM; i++) {
        int r = rowBase + ty * TM + i;
        if (r >= M_ROWS) continue;
        float* dst = g_logits + (size_t)r * N_COLS + vBase;
        if (fullCols) {
            *(float4*)(dst + 0) = make_float4(acc[i][0], acc[i][1], acc[i][2], acc[i][3]);
            *(float4*)(dst + 4) = make_float4(acc[i][4], acc[i][5], acc[i][6], acc[i][7]);
        } else {
            #pragma unroll
            for (int j = 0; j < TN; j++)
                if (vBase + j < N_COLS) dst[j] = acc[i][j];
        }
    }
}

// ---------------------------------------------------------------------------
// k2: per-row max and sum(exp(x - max)). One block per row (500 blocks).
// ---------------------------------------------------------------------------
__global__ __launch_bounds__(256)
void k2_stats() {
    const int r = blockIdx.x;
    const float* __restrict__ row = g_logits + (size_t)r * N_COLS;
    __shared__ float red[256];
    const int t = threadIdx.x;

    float m = -1e30f;
    for (int v = t * 4; v < N_COLS; v += 1024) {
        float4 x = *(const float4*)(row + v);
        m = fmaxf(m, fmaxf(fmaxf(x.x, x.y), fmaxf(x.z, x.w)));
    }
    red[t] = m;
    __syncthreads();
    for (int s = 128; s > 0; s >>= 1) {
        if (t < s) red[t] = fmaxf(red[t], red[t + s]);
        __syncthreads();
    }
    m = red[0];
    __syncthreads();

    float sum = 0.0f;
    for (int v = t * 4; v < N_COLS; v += 1024) {
        float4 x = *(const float4*)(row + v);
        sum += __expf(x.x - m) + __expf(x.y - m) + __expf(x.z - m) + __expf(x.w - m);
    }
    red[t] = sum;
    __syncthreads();
    for (int s = 128; s > 0; s >>= 1) {
        if (t < s) red[t] += red[t + s];
        __syncthreads();
    }
    if (t == 0) { g_rowmax[r] = m; g_rowsum[r] = red[0]; }
}

// ---------------------------------------------------------------------------
// k2b: c[b,k] = theta[b,k] / S[t_b*50 + k].  One block, thread = batch row.
// ---------------------------------------------------------------------------
__global__ void k2b_coeff(const float* __restrict__ theta) {
    const int b  = threadIdx.x;           // 256 threads
    const int r0 = g_tidx[b] * NTOPICS;
    #pragma unroll
    for (int k = 0; k < NTOPICS; k++)
        g_c[b * NTOPICS + k] = theta[b * NTOPICS + k] / g_rowsum[r0 + k];
}

// ---------------------------------------------------------------------------
// k3: out[b, v] = sum_k c[b,k] * exp(L[t_b*50+k, v] - m[.])
// Block = 16 V-columns x all 256 batch rows. eb tile staged in smem with
// stride 18 (bank-conflict-free across the 10 time slices, float2-aligned).
// 50000 % 16 == 0 -> no column guards.
// ---------------------------------------------------------------------------
#define VT  16
#define EBS 18

__global__ __launch_bounds__(256)
void k3_out(float* __restrict__ out) {
    __shared__ float eb[M_ROWS * EBS];    // 36 KB
    const int v0  = blockIdx.x * VT;
    const int tid = threadIdx.x;

    for (int i = tid; i < M_ROWS * VT; i += 256) {
        const int r = i / VT;
        const int v = i - r * VT;
        eb[r * EBS + v] = __expf(g_logits[(size_t)r * N_COLS + v0 + v] - g_rowmax[r]);
    }
    __syncthreads();

    const int b  = tid;
    const int rb = g_tidx[b] * NTOPICS;
    float creg[NTOPICS];
    #pragma unroll
    for (int k = 0; k < NTOPICS; k++) creg[k] = g_c[b * NTOPICS + k];

    #pragma unroll
    for (int vv = 0; vv < VT; vv += 2) {
        float2 a = make_float2(0.f, 0.f);
        #pragma unroll
        for (int k = 0; k < NTOPICS; k++) {
            float2 e = *(const float2*)&eb[(rb + k) * EBS + vv];
            a.x += creg[k] * e.x;
            a.y += creg[k] * e.y;
        }
        *(float2*)(out + (size_t)b * N_COLS + v0 + vv) = a;
    }
}

// ---------------------------------------------------------------------------
// kernel_launch
// ---------------------------------------------------------------------------
extern "C" void kernel_launch(void* const* d_in, const int* in_sizes, int n_in,
                              void* d_out, int out_size) {
    // Identify inputs by element count (robust to ordering):
    //   theta 256*50=12800, W 50000*1024=51200000, E 10*50*1024=512000, tix 256
    const float* theta = nullptr;
    const float* W     = nullptr;
    const float* E     = nullptr;
    const int*   tix   = nullptr;
    for (int i = 0; i < n_in; i++) {
        switch (in_sizes[i]) {
            case 12800:    theta = (const float*)d_in[i]; break;
            case 51200000: W     = (const float*)d_in[i]; break;
            case 512000:   E     = (const float*)d_in[i]; break;
            case 256:      tix   = (const int*)d_in[i];   break;
            default: break;
        }
    }
    float* out = (float*)d_out;

    k0_index<<<1, 256>>>(tix);

    dim3 g1((N_COLS + BN - 1) / BN, (M_ROWS + BM - 1) / BM);   // (391, 4)
    k1_gemm<<<g1, 256>>>(E, W);

    k2_stats<<<M_ROWS, 256>>>();
    k2b_coeff<<<1, 256>>>(theta);
    k3_out<<<N_COLS / VT, 256>>>(out);
}

// round 5
// speedup vs baseline: 2.1436x; 2.1436x over previous
#include <cuda_runtime.h>
#include <cuda_fp16.h>
#include <math.h>
#include <stdint.h>

// Problem dims
#define TSLICES 10
#define NTOPICS 50
#define M_ROWS  500
#define M_PAD   512
#define N_COLS  50000
#define N_PAD   50048          // 391 strips of 128
#define K_DIM   1024
#define BATCH   256

#define NSTRIP  391
#define CTA_M   256
#define CTA_N   128
#define KSTEP   64
#define NSTAGE  (K_DIM / KSTEP)   // 16

// ---------------------------------------------------------------------------
// Scratch (device globals)
// ---------------------------------------------------------------------------
__device__ float g_logits[(size_t)M_ROWS * N_COLS];          // 100 MB
__device__ float g_rowmax[M_ROWS];
__device__ float g_rowsum[M_ROWS];
__device__ float g_c[BATCH * NTOPICS];
__device__ int   g_tidx[BATCH];

__device__ __align__(16) __half g_Wh[(size_t)N_PAD * K_DIM]; // 102.5 MB
__device__ __align__(16) __half g_Wl[(size_t)N_PAD * K_DIM]; // 102.5 MB
__device__ __align__(16) __half g_Eh[(size_t)M_PAD * K_DIM]; // 1 MB
__device__ __align__(16) __half g_El[(size_t)M_PAD * K_DIM]; // 1 MB

// ---------------------------------------------------------------------------
// PTX helpers (ALL base-target sm_80/90 instructions — no 'a'-gated features)
// ---------------------------------------------------------------------------
__device__ __forceinline__ uint32_t s2u(const void* p) {
    uint32_t a;
    asm("{ .reg .u64 t; cvta.to.shared.u64 t, %1; cvt.u32.u64 %0, t; }" : "=r"(a) : "l"(p));
    return a;
}
__device__ __forceinline__ void cpasync16(uint32_t saddr, const void* gaddr) {
    asm volatile("cp.async.cg.shared.global [%0], [%1], 16;" :: "r"(saddr), "l"(gaddr) : "memory");
}
#define CP_COMMIT() asm volatile("cp.async.commit_group;" ::: "memory")
#define CP_WAIT(n)  asm volatile("cp.async.wait_group %0;" :: "n"(n) : "memory")

__device__ __forceinline__ void ldsm_x4(uint32_t* r, uint32_t a) {
    asm volatile("ldmatrix.sync.aligned.m8n8.x4.shared.b16 {%0,%1,%2,%3}, [%4];"
                 : "=r"(r[0]), "=r"(r[1]), "=r"(r[2]), "=r"(r[3]) : "r"(a));
}
__device__ __forceinline__ void ldsm_x2(uint32_t* r, uint32_t a) {
    asm volatile("ldmatrix.sync.aligned.m8n8.x2.shared.b16 {%0,%1}, [%2];"
                 : "=r"(r[0]), "=r"(r[1]) : "r"(a));
}
__device__ __forceinline__ void mma16816(float* c, const uint32_t* a, const uint32_t* b) {
    asm volatile("mma.sync.aligned.m16n8k16.row.col.f32.f16.f16.f32 "
                 "{%0,%1,%2,%3}, {%4,%5,%6,%7}, {%8,%9}, {%0,%1,%2,%3};"
                 : "+f"(c[0]), "+f"(c[1]), "+f"(c[2]), "+f"(c[3])
                 : "r"(a[0]), "r"(a[1]), "r"(a[2]), "r"(a[3]), "r"(b[0]), "r"(b[1]));
}
#define SWZ(o) ((o) ^ (((o) >> 3) & 0x70))

// ---------------------------------------------------------------------------
// k0: normalize time_index (int64 vs int32 runtime detection)
// ---------------------------------------------------------------------------
__global__ void k0_index(const int* __restrict__ tix_words) {
    __shared__ int s_nonzero;
    int t = threadIdx.x;
    if (t == 0) s_nonzero = 0;
    __syncthreads();
    if ((t & 1) && tix_words[t] != 0) atomicOr(&s_nonzero, 1);
    __syncthreads();
    bool is64 = (s_nonzero == 0);
    g_tidx[t] = is64 ? tix_words[2 * t] : tix_words[t];
}

// ---------------------------------------------------------------------------
// Split helpers: x = hi + lo in fp16, |x - hi - lo| <= 2^-22 |x|
// ---------------------------------------------------------------------------
__device__ __forceinline__ void split8(const float* x, uint32_t* hw, uint32_t* lw) {
    #pragma unroll
    for (int i = 0; i < 4; i++) {
        __half h0 = __float2half_rn(x[2*i]);
        __half l0 = __float2half_rn(x[2*i]   - __half2float(h0));
        __half h1 = __float2half_rn(x[2*i+1]);
        __half l1 = __float2half_rn(x[2*i+1] - __half2float(h1));
        hw[i] = (uint32_t)__half_as_ushort(h0) | ((uint32_t)__half_as_ushort(h1) << 16);
        lw[i] = (uint32_t)__half_as_ushort(l0) | ((uint32_t)__half_as_ushort(l1) << 16);
    }
}

// prepW: W fp32 [50000][1024] -> g_Wh/g_Wl half [50048][1024] (rows >= 50000 zero)
__global__ __launch_bounds__(256) void prepW(const float* __restrict__ W) {
    int idx = blockIdx.x * 256 + threadIdx.x;      // N_PAD*128 threads
    int v = idx >> 7, g = idx & 127;               // g: 8-elem group
    float x[8];
    if (v < N_COLS) {
        const float4* p = (const float4*)(W + (size_t)v * K_DIM + g * 8);
        float4 a = p[0], b = p[1];
        x[0]=a.x; x[1]=a.y; x[2]=a.z; x[3]=a.w; x[4]=b.x; x[5]=b.y; x[6]=b.z; x[7]=b.w;
    } else {
        #pragma unroll
        for (int i = 0; i < 8; i++) x[i] = 0.0f;
    }
    uint32_t hw[4], lw[4];
    split8(x, hw, lw);
    size_t d = ((size_t)v * K_DIM + g * 8) >> 3;   // uint4 index
    ((uint4*)g_Wh)[d] = make_uint4(hw[0], hw[1], hw[2], hw[3]);
    ((uint4*)g_Wl)[d] = make_uint4(lw[0], lw[1], lw[2], lw[3]);
}

// prepE: E fp32 [500][1024] -> g_Eh/g_El half [512][1024] (rows >= 500 zero)
__global__ __launch_bounds__(256) void prepE(const float* __restrict__ E) {
    int idx = blockIdx.x * 256 + threadIdx.x;      // 512*128 threads
    int r = idx >> 7, g = idx & 127;
    float x[8];
    if (r < M_ROWS) {
        const float4* p = (const float4*)(E + (size_t)r * K_DIM + g * 8);
        float4 a = p[0], b = p[1];
        x[0]=a.x; x[1]=a.y; x[2]=a.z; x[3]=a.w; x[4]=b.x; x[5]=b.y; x[6]=b.z; x[7]=b.w;
    } else {
        #pragma unroll
        for (int i = 0; i < 8; i++) x[i] = 0.0f;
    }
    uint32_t hw[4], lw[4];
    split8(x, hw, lw);
    size_t d = ((size_t)r * K_DIM + g * 8) >> 3;
    ((uint4*)g_Eh)[d] = make_uint4(hw[0], hw[1], hw[2], hw[3]);
    ((uint4*)g_El)[d] = make_uint4(lw[0], lw[1], lw[2], lw[3]);
}

// ---------------------------------------------------------------------------
// kgemm: HMMA (mma.sync m16n8k16 f16) GEMM with fp16 hi/lo 3-product split.
//   L[r, v] = E[r,:] . W[v,:]  accumulated fp32.
// CTA: 256 M-rows x 128 N-cols. 8 warps, each 64x64. K-step 64, double-buffered
// cp.async. Smem tiles swizzled (16B-chunk XOR) for conflict-free ldmatrix.
// Smem/stage: Ah 32K | Al 32K | Bh 16K | Bl 16K = 96K; x2 stages = 192K.
// ---------------------------------------------------------------------------
#define ST_STRIDE 98304
#define AH_OFF 0
#define AL_OFF 32768
#define BH_OFF 65536
#define BL_OFF 81920
#define GEMM_SMEM (2 * ST_STRIDE)

__device__ __forceinline__ void issue_stage(uint32_t sb, int buf, int s,
                                            int m0, int n0, int tid) {
    const int k0 = s * KSTEP;
    uint32_t base = sb + buf * ST_STRIDE;
    // A tiles: 256 rows x 128B  (2048 16B-chunks each for hi/lo)
    #pragma unroll
    for (int i = 0; i < 8; i++) {
        int cid = tid + i * 256;
        int row = cid >> 3, c = cid & 7;
        uint32_t sw = SWZ((uint32_t)(row * 128 + c * 16));
        const __half* gh = g_Eh + (size_t)(m0 + row) * K_DIM + k0 + c * 8;
        const __half* gl = g_El + (size_t)(m0 + row) * K_DIM + k0 + c * 8;
        cpasync16(base + AH_OFF + sw, gh);
        cpasync16(base + AL_OFF + sw, gl);
    }
    // B tiles: 128 rows x 128B (1024 chunks each)
    #pragma unroll
    for (int i = 0; i < 4; i++) {
        int cid = tid + i * 256;
        int row = cid >> 3, c = cid & 7;
        uint32_t sw = SWZ((uint32_t)(row * 128 + c * 16));
        cpasync16(base + BH_OFF + sw, g_Wh + (size_t)(n0 + row) * K_DIM + k0 + c * 8);
        cpasync16(base + BL_OFF + sw, g_Wl + (size_t)(n0 + row) * K_DIM + k0 + c * 8);
    }
}

__global__ __launch_bounds__(256, 1) void kgemm() {
    extern __shared__ char smem[];
    const uint32_t sb = s2u(smem);
    const int tid  = threadIdx.x;
    const int lane = tid & 31;
    const int wid  = tid >> 5;
    const int wm   = (wid >> 1) * 64;   // warp M offset: 0,64,128,192
    const int wn   = (wid & 1) * 64;    // warp N offset: 0,64
    const int m0   = blockIdx.y * CTA_M;
    const int n0   = blockIdx.x * CTA_N;

    float acc[4][8][4];
    #pragma unroll
    for (int i = 0; i < 4; i++)
        #pragma unroll
        for (int j = 0; j < 8; j++)
            #pragma unroll
            for (int q = 0; q < 4; q++) acc[i][j][q] = 0.0f;

    // per-thread invariant ldmatrix address components
    const int arow = wm + (lane & 15);          // A: row within tile
    const int acol = (lane >> 4) << 4;          // A: byte col (0 or 16)
    const int brow = wn + (lane & 7);           // B: row within tile
    const int bcol = ((lane >> 3) & 1) << 4;    // B: byte col (0 or 16)

    issue_stage(sb, 0, 0, m0, n0, tid);
    CP_COMMIT();

    for (int s = 0; s < NSTAGE; s++) {
        const int buf = s & 1;
        if (s + 1 < NSTAGE) {
            issue_stage(sb, buf ^ 1, s + 1, m0, n0, tid);
            CP_COMMIT();
            CP_WAIT(1);
        } else {
            CP_WAIT(0);
        }
        __syncthreads();

        const uint32_t tb = sb + buf * ST_STRIDE;
        #pragma unroll
        for (int kk = 0; kk < 4; kk++) {
            const int kb = kk * 32;            // byte offset of this k16 within stage
            uint32_t a[4][4], a2[4][4], b[8][2];
            // Ah fragments
            #pragma unroll
            for (int i = 0; i < 4; i++) {
                uint32_t off = (uint32_t)((arow + i * 16) * 128 + kb + acol);
                ldsm_x4(a[i], tb + AH_OFF + SWZ(off));
            }
            // Bh fragments
            #pragma unroll
            for (int j = 0; j < 8; j++) {
                uint32_t off = (uint32_t)((brow + j * 8) * 128 + kb + bcol);
                ldsm_x2(b[j], tb + BH_OFF + SWZ(off));
            }
            // acc += Ah * Bh
            #pragma unroll
            for (int i = 0; i < 4; i++)
                #pragma unroll
                for (int j = 0; j < 8; j++) mma16816(acc[i][j], a[i], b[j]);
            // Al fragments
            #pragma unroll
            for (int i = 0; i < 4; i++) {
                uint32_t off = (uint32_t)((arow + i * 16) * 128 + kb + acol);
                ldsm_x4(a2[i], tb + AL_OFF + SWZ(off));
            }
            // acc += Al * Bh
            #pragma unroll
            for (int i = 0; i < 4; i++)
                #pragma unroll
                for (int j = 0; j < 8; j++) mma16816(acc[i][j], a2[i], b[j]);
            // Bl fragments (reuse b regs)
            #pragma unroll
            for (int j = 0; j < 8; j++) {
                uint32_t off = (uint32_t)((brow + j * 8) * 128 + kb + bcol);
                ldsm_x2(b[j], tb + BL_OFF + SWZ(off));
            }
            // acc += Ah * Bl
            #pragma unroll
            for (int i = 0; i < 4; i++)
                #pragma unroll
                for (int j = 0; j < 8; j++) mma16816(acc[i][j], a[i], b[j]);
        }
        __syncthreads();
    }

    // Epilogue: fragment (i,j): c0,c1 -> (row l/4, col 2(l%4)), c2,c3 -> row+8
    const int erow = m0 + wm + (lane >> 2);
    const int ecol0 = n0 + wn + 2 * (lane & 3);
    #pragma unroll
    for (int i = 0; i < 4; i++) {
        #pragma unroll
        for (int j = 0; j < 8; j++) {
            int cc = ecol0 + j * 8;
            if (cc >= N_COLS) continue;
            int r0 = erow + i * 16;
            if (r0 < M_ROWS)
                *(float2*)(g_logits + (size_t)r0 * N_COLS + cc) =
                    make_float2(acc[i][j][0], acc[i][j][1]);
            int r1 = r0 + 8;
            if (r1 < M_ROWS)
                *(float2*)(g_logits + (size_t)r1 * N_COLS + cc) =
                    make_float2(acc[i][j][2], acc[i][j][3]);
        }
    }
}

// ---------------------------------------------------------------------------
// k2: per-row max and sum(exp(x - max)). One block per row.
// ---------------------------------------------------------------------------
__global__ __launch_bounds__(256) void k2_stats() {
    const int r = blockIdx.x;
    const float* __restrict__ row = g_logits + (size_t)r * N_COLS;
    __shared__ float red[256];
    const int t = threadIdx.x;

    float m = -1e30f;
    for (int v = t * 4; v < N_COLS; v += 1024) {
        float4 x = *(const float4*)(row + v);
        m = fmaxf(m, fmaxf(fmaxf(x.x, x.y), fmaxf(x.z, x.w)));
    }
    red[t] = m;
    __syncthreads();
    for (int s = 128; s > 0; s >>= 1) {
        if (t < s) red[t] = fmaxf(red[t], red[t + s]);
        __syncthreads();
    }
    m = red[0];
    __syncthreads();

    float sum = 0.0f;
    for (int v = t * 4; v < N_COLS; v += 1024) {
        float4 x = *(const float4*)(row + v);
        sum += __expf(x.x - m) + __expf(x.y - m) + __expf(x.z - m) + __expf(x.w - m);
    }
    red[t] = sum;
    __syncthreads();
    for (int s = 128; s > 0; s >>= 1) {
        if (t < s) red[t] += red[t + s];
        __syncthreads();
    }
    if (t == 0) { g_rowmax[r] = m; g_rowsum[r] = red[0]; }
}

// ---------------------------------------------------------------------------
// k2b: c[b,k] = theta[b,k] / S[t_b*50+k]
// ---------------------------------------------------------------------------
__global__ void k2b_coeff(const float* __restrict__ theta) {
    int i = blockIdx.x * 256 + threadIdx.x;     // 50 blocks x 256 = 12800
    int b = i / NTOPICS, k = i - b * NTOPICS;
    g_c[i] = theta[i] / g_rowsum[g_tidx[b] * NTOPICS + k];
}

// ---------------------------------------------------------------------------
// k3: out[b,v] = sum_k c[b,k] * exp(L[t_b*50+k, v] - m[.])
// ---------------------------------------------------------------------------
#define VT  16
#define EBS 18

__global__ __launch_bounds__(256) void k3_out(float* __restrict__ out) {
    __shared__ float eb[M_ROWS * EBS];
    const int v0  = blockIdx.x * VT;
    const int tid = threadIdx.x;

    for (int i = tid; i < M_ROWS * VT; i += 256) {
        const int r = i / VT;
        const int v = i - r * VT;
        eb[r * EBS + v] = __expf(g_logits[(size_t)r * N_COLS + v0 + v] - g_rowmax[r]);
    }
    __syncthreads();

    const int b  = tid;
    const int rb = g_tidx[b] * NTOPICS;
    float creg[NTOPICS];
    #pragma unroll
    for (int k = 0; k < NTOPICS; k++) creg[k] = g_c[b * NTOPICS + k];

    #pragma unroll
    for (int vv = 0; vv < VT; vv += 2) {
        float2 a = make_float2(0.f, 0.f);
        #pragma unroll
        for (int k = 0; k < NTOPICS; k++) {
            float2 e = *(const float2*)&eb[(rb + k) * EBS + vv];
            a.x += creg[k] * e.x;
            a.y += creg[k] * e.y;
        }
        *(float2*)(out + (size_t)b * N_COLS + v0 + vv) = a;
    }
}

// ---------------------------------------------------------------------------
// kernel_launch
// ---------------------------------------------------------------------------
extern "C" void kernel_launch(void* const* d_in, const int* in_sizes, int n_in,
                              void* d_out, int out_size) {
    const float* theta = nullptr;
    const float* W     = nullptr;
    const float* E     = nullptr;
    const int*   tix   = nullptr;
    for (int i = 0; i < n_in; i++) {
        switch (in_sizes[i]) {
            case 12800:    theta = (const float*)d_in[i]; break;
            case 51200000: W     = (const float*)d_in[i]; break;
            case 512000:   E     = (const float*)d_in[i]; break;
            case 256:      tix   = (const int*)d_in[i];   break;
            default: break;
        }
    }
    float* out = (float*)d_out;

    static int smem_set = 0;
    if (!smem_set) {
        cudaFuncSetAttribute(kgemm, cudaFuncAttributeMaxDynamicSharedMemorySize, GEMM_SMEM);
        smem_set = 1;
    }

    k0_index<<<1, 256>>>(tix);
    prepW<<<(N_PAD * 128) / 256, 256>>>(W);     // 25024 blocks
    prepE<<<(M_PAD * 128) / 256, 256>>>(E);     // 256 blocks

    dim3 gg(NSTRIP, M_PAD / CTA_M);             // (391, 2)
    kgemm<<<gg, 256, GEMM_SMEM>>>();

    k2_stats<<<M_ROWS, 256>>>();
    k2b_coeff<<<BATCH * NTOPICS / 256, 256>>>(theta);
    k3_out<<<N_COLS / VT, 256>>>(out);
}

// round 6
// speedup vs baseline: 2.3319x; 1.0878x over previous
#include <cuda_runtime.h>
#include <cuda_fp16.h>
#include <math.h>
#include <stdint.h>

// Problem dims
#define TSLICES 10
#define NTOPICS 50
#define M_ROWS  500
#define M_PAD   512
#define N_COLS  50000
#define N_PAD   50048          // 391 strips of 128
#define K_DIM   1024
#define BATCH   256

#define NSTRIP  391
#define CTA_M   256
#define CTA_N   128
#define KSTEP   64
#define NSTAGE  (K_DIM / KSTEP)   // 16

// ---------------------------------------------------------------------------
// Scratch (device globals)
// ---------------------------------------------------------------------------
__device__ float g_logits[(size_t)M_ROWS * N_COLS];          // 100 MB
__device__ float g_rowmax[M_ROWS];
__device__ float g_rowsum[M_ROWS];
__device__ float g_c[BATCH * NTOPICS];
__device__ int   g_tidx[BATCH];
__device__ int   g_order[BATCH];                             // batches sorted by t
__device__ float g_pmax[(size_t)M_PAD * 2 * NSTRIP];         // per (row, strip-half)
__device__ float g_psum[(size_t)M_PAD * 2 * NSTRIP];

__device__ __align__(16) __half g_Eh[(size_t)M_PAD * K_DIM]; // 1 MB
__device__ __align__(16) __half g_El[(size_t)M_PAD * K_DIM]; // 1 MB

// ---------------------------------------------------------------------------
// PTX helpers (base-target sm_80/90 instructions only)
// ---------------------------------------------------------------------------
__device__ __forceinline__ uint32_t s2u(const void* p) {
    uint32_t a;
    asm("{ .reg .u64 t; cvta.to.shared.u64 t, %1; cvt.u32.u64 %0, t; }" : "=r"(a) : "l"(p));
    return a;
}
__device__ __forceinline__ void cpasync16(uint32_t saddr, const void* gaddr) {
    asm volatile("cp.async.cg.shared.global [%0], [%1], 16;" :: "r"(saddr), "l"(gaddr) : "memory");
}
#define CP_COMMIT() asm volatile("cp.async.commit_group;" ::: "memory")
#define CP_WAIT(n)  asm volatile("cp.async.wait_group %0;" :: "n"(n) : "memory")

__device__ __forceinline__ void ldsm_x4(uint32_t* r, uint32_t a) {
    asm volatile("ldmatrix.sync.aligned.m8n8.x4.shared.b16 {%0,%1,%2,%3}, [%4];"
                 : "=r"(r[0]), "=r"(r[1]), "=r"(r[2]), "=r"(r[3]) : "r"(a));
}
__device__ __forceinline__ void ldsm_x2(uint32_t* r, uint32_t a) {
    asm volatile("ldmatrix.sync.aligned.m8n8.x2.shared.b16 {%0,%1}, [%2];"
                 : "=r"(r[0]), "=r"(r[1]) : "r"(a));
}
__device__ __forceinline__ void mma16816(float* c, const uint32_t* a, const uint32_t* b) {
    asm volatile("mma.sync.aligned.m16n8k16.row.col.f32.f16.f16.f32 "
                 "{%0,%1,%2,%3}, {%4,%5,%6,%7}, {%8,%9}, {%0,%1,%2,%3};"
                 : "+f"(c[0]), "+f"(c[1]), "+f"(c[2]), "+f"(c[3])
                 : "r"(a[0]), "r"(a[1]), "r"(a[2]), "r"(a[3]), "r"(b[0]), "r"(b[1]));
}
__device__ __forceinline__ void sts128(uint32_t a, uint32_t x, uint32_t y, uint32_t z, uint32_t w) {
    asm volatile("st.shared.v4.b32 [%0], {%1,%2,%3,%4};" :: "r"(a), "r"(x), "r"(y), "r"(z), "r"(w) : "memory");
}
#define SWZ(o) ((o) ^ (((o) >> 3) & 0x70))

// ---------------------------------------------------------------------------
// k0: normalize time_index (int64 vs int32 runtime detect) + counting sort
// ---------------------------------------------------------------------------
__global__ void k0_index(const int* __restrict__ tix_words) {
    __shared__ int s_nonzero;
    __shared__ int tval[BATCH];
    int t = threadIdx.x;
    if (t == 0) s_nonzero = 0;
    __syncthreads();
    if ((t & 1) && tix_words[t] != 0) atomicOr(&s_nonzero, 1);
    __syncthreads();
    int v = (s_nonzero == 0) ? tix_words[2 * t] : tix_words[t];
    g_tidx[t] = v;
    tval[t] = v;
    __syncthreads();
    if (t == 0) {
        int cnt[TSLICES], off[TSLICES];
        #pragma unroll
        for (int s = 0; s < TSLICES; s++) cnt[s] = 0;
        for (int i = 0; i < BATCH; i++) cnt[tval[i]]++;
        int a = 0;
        #pragma unroll
        for (int s = 0; s < TSLICES; s++) { off[s] = a; a += cnt[s]; }
        for (int i = 0; i < BATCH; i++) g_order[off[tval[i]]++] = i;
    }
}

// ---------------------------------------------------------------------------
// fp16 hi/lo split helpers
// ---------------------------------------------------------------------------
__device__ __forceinline__ void split8(const float* x, uint32_t* hw, uint32_t* lw) {
    #pragma unroll
    for (int i = 0; i < 4; i++) {
        __half h0 = __float2half_rn(x[2*i]);
        __half l0 = __float2half_rn(x[2*i]   - __half2float(h0));
        __half h1 = __float2half_rn(x[2*i+1]);
        __half l1 = __float2half_rn(x[2*i+1] - __half2float(h1));
        hw[i] = (uint32_t)__half_as_ushort(h0) | ((uint32_t)__half_as_ushort(h1) << 16);
        lw[i] = (uint32_t)__half_as_ushort(l0) | ((uint32_t)__half_as_ushort(l1) << 16);
    }
}

// prepE: E fp32 [500][1024] -> g_Eh/g_El half [512][1024] (rows >= 500 zero)
__global__ __launch_bounds__(256) void prepE(const float* __restrict__ E) {
    int idx = blockIdx.x * 256 + threadIdx.x;      // 512*128 threads
    int r = idx >> 7, g = idx & 127;
    float x[8];
    if (r < M_ROWS) {
        const float4* p = (const float4*)(E + (size_t)r * K_DIM + g * 8);
        float4 a = p[0], b = p[1];
        x[0]=a.x; x[1]=a.y; x[2]=a.z; x[3]=a.w; x[4]=b.x; x[5]=b.y; x[6]=b.z; x[7]=b.w;
    } else {
        #pragma unroll
        for (int i = 0; i < 8; i++) x[i] = 0.0f;
    }
    uint32_t hw[4], lw[4];
    split8(x, hw, lw);
    size_t d = ((size_t)r * K_DIM + g * 8) >> 3;
    ((uint4*)g_Eh)[d] = make_uint4(hw[0], hw[1], hw[2], hw[3]);
    ((uint4*)g_El)[d] = make_uint4(lw[0], lw[1], lw[2], lw[3]);
}

// ---------------------------------------------------------------------------
// kgemm: HMMA GEMM, fp16 hi/lo 3-product split.  W loaded fp32 and split
// in-kernel (LDG -> cvt -> STS, pipelined in 2 chunks).  A via cp.async from
// pre-split g_Eh/g_El.  Epilogue writes logits AND per-(row, 64col) partial
// softmax stats (max, sum-exp).
// Smem/stage: Ah 32K | Al 32K | Bh 16K | Bl 16K = 96K; x2 stages = 192K.
// ---------------------------------------------------------------------------
#define ST_STRIDE 98304
#define AH_OFF 0
#define AL_OFF 32768
#define BH_OFF 65536
#define BL_OFF 81920
#define GEMM_SMEM (2 * ST_STRIDE)

__device__ __forceinline__ void issueA(uint32_t sb, int buf, int s, int m0, int tid) {
    const int k0 = s * KSTEP;
    uint32_t base = sb + buf * ST_STRIDE;
    #pragma unroll
    for (int i = 0; i < 8; i++) {
        int cid = tid + i * 256;
        int row = cid >> 3, c = cid & 7;
        uint32_t sw = SWZ((uint32_t)(row * 128 + c * 16));
        cpasync16(base + AH_OFF + sw, g_Eh + (size_t)(m0 + row) * K_DIM + k0 + c * 8);
        cpasync16(base + AL_OFF + sw, g_El + (size_t)(m0 + row) * K_DIM + k0 + c * 8);
    }
}

// Load 16 fp32 of W for (row, half, chunk c) of stage s
__device__ __forceinline__ void ldgB(const float* __restrict__ W, int n0, int s,
                                     int row, int half, int c, float4* r) {
    if (n0 + row < N_COLS) {
        const float4* p = (const float4*)(W + (size_t)(n0 + row) * K_DIM +
                                          s * KSTEP + half * 32 + c * 16);
        #pragma unroll
        for (int q = 0; q < 4; q++) r[q] = p[q];
    } else {
        #pragma unroll
        for (int q = 0; q < 4; q++) r[q] = make_float4(0.f, 0.f, 0.f, 0.f);
    }
}

// Convert 16 fp32 -> hi/lo halfs, store swizzled to Bh/Bl of buffer `base`
__device__ __forceinline__ void stsB(uint32_t base, int row, int half, int c, const float4* r) {
    uint32_t hw[8], lw[8];
    const float* x = (const float*)r;
    #pragma unroll
    for (int i = 0; i < 8; i++) {
        __half h0 = __float2half_rn(x[2*i]);
        __half l0 = __float2half_rn(x[2*i]   - __half2float(h0));
        __half h1 = __float2half_rn(x[2*i+1]);
        __half l1 = __float2half_rn(x[2*i+1] - __half2float(h1));
        hw[i] = (uint32_t)__half_as_ushort(h0) | ((uint32_t)__half_as_ushort(h1) << 16);
        lw[i] = (uint32_t)__half_as_ushort(l0) | ((uint32_t)__half_as_ushort(l1) << 16);
    }
    uint32_t byte0 = (uint32_t)(row * 128 + half * 64 + c * 32);
    uint32_t s0 = SWZ(byte0), s1 = SWZ(byte0 + 16);
    sts128(base + BH_OFF + s0, hw[0], hw[1], hw[2], hw[3]);
    sts128(base + BH_OFF + s1, hw[4], hw[5], hw[6], hw[7]);
    sts128(base + BL_OFF + s0, lw[0], lw[1], lw[2], lw[3]);
    sts128(base + BL_OFF + s1, lw[4], lw[5], lw[6], lw[7]);
}

__global__ __launch_bounds__(256, 1) void kgemm(const float* __restrict__ W) {
    extern __shared__ char smem[];
    const uint32_t sb = s2u(smem);
    const int tid  = threadIdx.x;
    const int lane = tid & 31;
    const int wid  = tid >> 5;
    const int wm   = (wid >> 1) * 64;   // warp M offset: 0,64,128,192
    const int wn   = (wid & 1) * 64;    // warp N offset: 0,64
    const int m0   = blockIdx.y * CTA_M;
    const int n0   = blockIdx.x * CTA_N;
    const int brow  = tid >> 1;         // B loader: row 0..127
    const int bhalf = tid & 1;          // B loader: k-half

    float acc[4][8][4];
    #pragma unroll
    for (int i = 0; i < 4; i++)
        #pragma unroll
        for (int j = 0; j < 8; j++)
            #pragma unroll
            for (int q = 0; q < 4; q++) acc[i][j][q] = 0.0f;

    const int arow = wm + (lane & 15);
    const int acol = (lane >> 4) << 4;
    const int brf  = wn + (lane & 7);
    const int bcf  = ((lane >> 3) & 1) << 4;

    // prologue: stage 0
    issueA(sb, 0, 0, m0, tid); CP_COMMIT();
    {
        float4 r0[4], r1[4];
        ldgB(W, n0, 0, brow, bhalf, 0, r0);
        ldgB(W, n0, 0, brow, bhalf, 1, r1);
        stsB(sb, brow, bhalf, 0, r0);
        stsB(sb, brow, bhalf, 1, r1);
    }
    CP_WAIT(0);
    __syncthreads();

    float4 breg[4];
    for (int s = 0; s < NSTAGE; s++) {
        const int buf = s & 1;
        const uint32_t tb = sb + buf * ST_STRIDE;
        const uint32_t nb = sb + (buf ^ 1) * ST_STRIDE;
        const bool more = (s + 1 < NSTAGE);
        if (more) {
            issueA(sb, buf ^ 1, s + 1, m0, tid); CP_COMMIT();
            ldgB(W, n0, s + 1, brow, bhalf, 0, breg);
        }
        #pragma unroll
        for (int kk = 0; kk < 4; kk++) {
            if (more && kk == 1) {
                stsB(nb, brow, bhalf, 0, breg);
                ldgB(W, n0, s + 1, brow, bhalf, 1, breg);
            }
            if (more && kk == 3) stsB(nb, brow, bhalf, 1, breg);

            const int kb = kk * 32;
            uint32_t a[4][4], a2[4][4], b[8][2];
            #pragma unroll
            for (int i = 0; i < 4; i++) {
                uint32_t off = (uint32_t)((arow + i * 16) * 128 + kb + acol);
                ldsm_x4(a[i], tb + AH_OFF + SWZ(off));
            }
            #pragma unroll
            for (int j = 0; j < 8; j++) {
                uint32_t off = (uint32_t)((brf + j * 8) * 128 + kb + bcf);
                ldsm_x2(b[j], tb + BH_OFF + SWZ(off));
            }
            #pragma unroll
            for (int i = 0; i < 4; i++)
                #pragma unroll
                for (int j = 0; j < 8; j++) mma16816(acc[i][j], a[i], b[j]);
            #pragma unroll
            for (int i = 0; i < 4; i++) {
                uint32_t off = (uint32_t)((arow + i * 16) * 128 + kb + acol);
                ldsm_x4(a2[i], tb + AL_OFF + SWZ(off));
            }
            #pragma unroll
            for (int i = 0; i < 4; i++)
                #pragma unroll
                for (int j = 0; j < 8; j++) mma16816(acc[i][j], a2[i], b[j]);
            #pragma unroll
            for (int j = 0; j < 8; j++) {
                uint32_t off = (uint32_t)((brf + j * 8) * 128 + kb + bcf);
                ldsm_x2(b[j], tb + BL_OFF + SWZ(off));
            }
            #pragma unroll
            for (int i = 0; i < 4; i++)
                #pragma unroll
                for (int j = 0; j < 8; j++) mma16816(acc[i][j], a[i], b[j]);
        }
        if (more) CP_WAIT(0);
        __syncthreads();
    }

    // ---- Epilogue part 1: logits store ----
    const int erow  = m0 + wm + (lane >> 2);
    const int ecol0 = n0 + wn + 2 * (lane & 3);
    #pragma unroll
    for (int i = 0; i < 4; i++) {
        #pragma unroll
        for (int j = 0; j < 8; j++) {
            int cc = ecol0 + j * 8;
            if (cc >= N_COLS) continue;
            int r0 = erow + i * 16;
            if (r0 < M_ROWS)
                *(float2*)(g_logits + (size_t)r0 * N_COLS + cc) =
                    make_float2(acc[i][j][0], acc[i][j][1]);
            int r1 = r0 + 8;
            if (r1 < M_ROWS)
                *(float2*)(g_logits + (size_t)r1 * N_COLS + cc) =
                    make_float2(acc[i][j][2], acc[i][j][3]);
        }
    }

    // ---- Epilogue part 2: partial softmax stats (max, sum-exp per 64 cols) ----
    const int part = blockIdx.x * 2 + (wn >> 6);
    #pragma unroll
    for (int i = 0; i < 4; i++) {
        #pragma unroll
        for (int h = 0; h < 2; h++) {
            int row = m0 + wm + (lane >> 2) + i * 16 + h * 8;
            float mloc = -1e30f;
            #pragma unroll
            for (int j = 0; j < 8; j++) {
                int cc = ecol0 + j * 8;
                if (cc < N_COLS) {   // cc even, N_COLS even -> cc+1 also valid
                    mloc = fmaxf(mloc, fmaxf(acc[i][j][2*h], acc[i][j][2*h+1]));
                }
            }
            mloc = fmaxf(mloc, __shfl_xor_sync(0xFFFFFFFF, mloc, 1));
            mloc = fmaxf(mloc, __shfl_xor_sync(0xFFFFFFFF, mloc, 2));
            float sloc = 0.0f;
            #pragma unroll
            for (int j = 0; j < 8; j++) {
                int cc = ecol0 + j * 8;
                if (cc < N_COLS)
                    sloc += __expf(acc[i][j][2*h] - mloc) + __expf(acc[i][j][2*h+1] - mloc);
            }
            sloc += __shfl_xor_sync(0xFFFFFFFF, sloc, 1);
            sloc += __shfl_xor_sync(0xFFFFFFFF, sloc, 2);
            if ((lane & 3) == 0) {
                g_pmax[(size_t)row * (2 * NSTRIP) + part] = mloc;
                g_psum[(size_t)row * (2 * NSTRIP) + part] = sloc;
            }
        }
    }
}

// ---------------------------------------------------------------------------
// k2r: merge 782 partials per row -> rowmax, rowsum (with rescale)
// ---------------------------------------------------------------------------
__global__ __launch_bounds__(256) void k2r() {
    const int r = blockIdx.x;
    const float* pm = g_pmax + (size_t)r * (2 * NSTRIP);
    const float* ps = g_psum + (size_t)r * (2 * NSTRIP);
    __shared__ float red[256];
    const int t = threadIdx.x;

    float m = -1e30f;
    for (int i = t; i < 2 * NSTRIP; i += 256) m = fmaxf(m, pm[i]);
    red[t] = m;
    __syncthreads();
    for (int s = 128; s > 0; s >>= 1) {
        if (t < s) red[t] = fmaxf(red[t], red[t + s]);
        __syncthreads();
    }
    m = red[0];
    __syncthreads();

    float sum = 0.0f;
    for (int i = t; i < 2 * NSTRIP; i += 256) sum += ps[i] * __expf(pm[i] - m);
    red[t] = sum;
    __syncthreads();
    for (int s = 128; s > 0; s >>= 1) {
        if (t < s) red[t] += red[t + s];
        __syncthreads();
    }
    if (t == 0) { g_rowmax[r] = m; g_rowsum[r] = red[0]; }
}

// ---------------------------------------------------------------------------
// k2b: c[b,k] = theta[b,k] / S[t_b*50+k]
// ---------------------------------------------------------------------------
__global__ void k2b_coeff(const float* __restrict__ theta) {
    int i = blockIdx.x * 256 + threadIdx.x;
    int b = i / NTOPICS, k = i - b * NTOPICS;
    g_c[i] = theta[i] / g_rowsum[g_tidx[b] * NTOPICS + k];
}

// ---------------------------------------------------------------------------
// k3: out[b,v] = sum_k c[b,k] * exp(L[t_b*50+k, v] - m[.])
// Threads process time-sorted batches -> warp lanes share t -> smem broadcast.
// ---------------------------------------------------------------------------
#define VT  32
#define EBS 34
#define K3_SMEM ((M_ROWS * EBS + M_ROWS) * 4)

__global__ __launch_bounds__(256) void k3_out(float* __restrict__ out) {
    extern __shared__ float sm[];
    float* eb = sm;                   // [500][34]
    float* rm = sm + M_ROWS * EBS;    // [500]
    const int v0  = blockIdx.x * VT;
    const int tid = threadIdx.x;

    for (int r = tid; r < M_ROWS; r += 256) rm[r] = g_rowmax[r];
    __syncthreads();

    for (int i = tid; i < M_ROWS * VT; i += 256) {
        int r = i >> 5, v = i & 31;
        int vc = v0 + v;
        float x = (vc < N_COLS) ? g_logits[(size_t)r * N_COLS + vc] : -1e30f;
        eb[r * EBS + v] = __expf(x - rm[r]);
    }
    __syncthreads();

    const int b  = g_order[tid];
    const int rb = g_tidx[b] * NTOPICS;
    float creg[NTOPICS];
    #pragma unroll
    for (int k = 0; k < NTOPICS; k++) creg[k] = g_c[b * NTOPICS + k];

    float* orow = out + (size_t)b * N_COLS + v0;
    #pragma unroll
    for (int vv = 0; vv < VT; vv += 2) {
        float2 a = make_float2(0.f, 0.f);
        #pragma unroll
        for (int k = 0; k < NTOPICS; k++) {
            float2 e = *(const float2*)&eb[(rb + k) * EBS + vv];
            a.x += creg[k] * e.x;
            a.y += creg[k] * e.y;
        }
        int vc = v0 + vv;
        if (vc + 1 < N_COLS)      *(float2*)(orow + vv) = a;
        else if (vc < N_COLS)     orow[vv] = a.x;
    }
}

// ---------------------------------------------------------------------------
// kernel_launch
// ---------------------------------------------------------------------------
extern "C" void kernel_launch(void* const* d_in, const int* in_sizes, int n_in,
                              void* d_out, int out_size) {
    const float* theta = nullptr;
    const float* W     = nullptr;
    const float* E     = nullptr;
    const int*   tix   = nullptr;
    for (int i = 0; i < n_in; i++) {
        switch (in_sizes[i]) {
            case 12800:    theta = (const float*)d_in[i]; break;
            case 51200000: W     = (const float*)d_in[i]; break;
            case 512000:   E     = (const float*)d_in[i]; break;
            case 256:      tix   = (const int*)d_in[i];   break;
            default: break;
        }
    }
    float* out = (float*)d_out;

    static int attr_set = 0;
    if (!attr_set) {
        cudaFuncSetAttribute(kgemm, cudaFuncAttributeMaxDynamicSharedMemorySize, GEMM_SMEM);
        cudaFuncSetAttribute(k3_out, cudaFuncAttributeMaxDynamicSharedMemorySize, K3_SMEM);
        attr_set = 1;
    }

    k0_index<<<1, 256>>>(tix);
    prepE<<<(M_PAD * 128) / 256, 256>>>(E);

    dim3 gg(NSTRIP, M_PAD / CTA_M);             // (391, 2)
    kgemm<<<gg, 256, GEMM_SMEM>>>(W);

    k2r<<<M_ROWS, 256>>>();
    k2b_coeff<<<BATCH * NTOPICS / 256, 256>>>(theta);
    k3_out<<<(N_COLS + VT - 1) / VT, 256, K3_SMEM>>>(out);   // 1563 blocks
}

// round 7
// speedup vs baseline: 2.4179x; 1.0369x over previous
#include <cuda_runtime.h>
#include <cuda_fp16.h>
#include <math.h>
#include <stdint.h>

// Problem dims
#define TSLICES 10
#define NTOPICS 50
#define M_ROWS  500
#define M_PAD   512
#define N_COLS  50000
#define N_PAD   50048          // 391 strips of 128
#define K_DIM   1024
#define BATCH   256

#define NSTRIP  391
#define CTA_M   256
#define CTA_N   128
#define KSTEP   64
#define NSTAGE  (K_DIM / KSTEP)   // 16

// ---------------------------------------------------------------------------
// Scratch (device globals)
// ---------------------------------------------------------------------------
__device__ float g_logits[(size_t)M_ROWS * N_COLS];          // 100 MB
__device__ float g_rowmax[M_ROWS];
__device__ float g_rowsum[M_ROWS];
__device__ float g_c[BATCH * NTOPICS];
__device__ int   g_tidx[BATCH];
__device__ int   g_order[BATCH];                             // batches sorted by t
__device__ float g_pmax[(size_t)M_PAD * 2 * NSTRIP];         // per (row, strip-half)
__device__ float g_psum[(size_t)M_PAD * 2 * NSTRIP];

__device__ __align__(16) __half g_Wh[(size_t)N_PAD * K_DIM]; // 102.5 MB
__device__ __align__(16) __half g_Wl[(size_t)N_PAD * K_DIM]; // 102.5 MB
__device__ __align__(16) __half g_Eh[(size_t)M_PAD * K_DIM]; // 1 MB
__device__ __align__(16) __half g_El[(size_t)M_PAD * K_DIM]; // 1 MB

// ---------------------------------------------------------------------------
// PTX helpers (base-target sm_80/90 instructions only)
// ---------------------------------------------------------------------------
__device__ __forceinline__ uint32_t s2u(const void* p) {
    uint32_t a;
    asm("{ .reg .u64 t; cvta.to.shared.u64 t, %1; cvt.u32.u64 %0, t; }" : "=r"(a) : "l"(p));
    return a;
}
__device__ __forceinline__ void cpasync16(uint32_t saddr, const void* gaddr) {
    asm volatile("cp.async.cg.shared.global [%0], [%1], 16;" :: "r"(saddr), "l"(gaddr) : "memory");
}
#define CP_COMMIT() asm volatile("cp.async.commit_group;" ::: "memory")
#define CP_WAIT(n)  asm volatile("cp.async.wait_group %0;" :: "n"(n) : "memory")

__device__ __forceinline__ void ldsm_x4(uint32_t* r, uint32_t a) {
    asm volatile("ldmatrix.sync.aligned.m8n8.x4.shared.b16 {%0,%1,%2,%3}, [%4];"
                 : "=r"(r[0]), "=r"(r[1]), "=r"(r[2]), "=r"(r[3]) : "r"(a));
}
__device__ __forceinline__ void ldsm_x2(uint32_t* r, uint32_t a) {
    asm volatile("ldmatrix.sync.aligned.m8n8.x2.shared.b16 {%0,%1}, [%2];"
                 : "=r"(r[0]), "=r"(r[1]) : "r"(a));
}
__device__ __forceinline__ void mma16816(float* c, const uint32_t* a, const uint32_t* b) {
    asm volatile("mma.sync.aligned.m16n8k16.row.col.f32.f16.f16.f32 "
                 "{%0,%1,%2,%3}, {%4,%5,%6,%7}, {%8,%9}, {%0,%1,%2,%3};"
                 : "+f"(c[0]), "+f"(c[1]), "+f"(c[2]), "+f"(c[3])
                 : "r"(a[0]), "r"(a[1]), "r"(a[2]), "r"(a[3]), "r"(b[0]), "r"(b[1]));
}
#define SWZ(o) ((o) ^ (((o) >> 3) & 0x70))

// ---------------------------------------------------------------------------
// k0: normalize time_index (int64 vs int32 runtime detect) + counting sort
// ---------------------------------------------------------------------------
__global__ void k0_index(const int* __restrict__ tix_words) {
    __shared__ int s_nonzero;
    __shared__ int tval[BATCH];
    int t = threadIdx.x;
    if (t == 0) s_nonzero = 0;
    __syncthreads();
    if ((t & 1) && tix_words[t] != 0) atomicOr(&s_nonzero, 1);
    __syncthreads();
    int v = (s_nonzero == 0) ? tix_words[2 * t] : tix_words[t];
    g_tidx[t] = v;
    tval[t] = v;
    __syncthreads();
    if (t == 0) {
        int cnt[TSLICES], off[TSLICES];
        #pragma unroll
        for (int s = 0; s < TSLICES; s++) cnt[s] = 0;
        for (int i = 0; i < BATCH; i++) cnt[tval[i]]++;
        int a = 0;
        #pragma unroll
        for (int s = 0; s < TSLICES; s++) { off[s] = a; a += cnt[s]; }
        for (int i = 0; i < BATCH; i++) g_order[off[tval[i]]++] = i;
    }
}

// ---------------------------------------------------------------------------
// fp16 hi/lo split helpers
// ---------------------------------------------------------------------------
__device__ __forceinline__ void split8(const float* x, uint32_t* hw, uint32_t* lw) {
    #pragma unroll
    for (int i = 0; i < 4; i++) {
        __half h0 = __float2half_rn(x[2*i]);
        __half l0 = __float2half_rn(x[2*i]   - __half2float(h0));
        __half h1 = __float2half_rn(x[2*i+1]);
        __half l1 = __float2half_rn(x[2*i+1] - __half2float(h1));
        hw[i] = (uint32_t)__half_as_ushort(h0) | ((uint32_t)__half_as_ushort(h1) << 16);
        lw[i] = (uint32_t)__half_as_ushort(l0) | ((uint32_t)__half_as_ushort(l1) << 16);
    }
}

// prepW: W fp32 [50000][1024] -> g_Wh/g_Wl half [50048][1024] (rows >= 50000 zero)
__global__ __launch_bounds__(256) void prepW(const float* __restrict__ W) {
    int idx = blockIdx.x * 256 + threadIdx.x;      // N_PAD*128 threads
    int v = idx >> 7, g = idx & 127;
    float x[8];
    if (v < N_COLS) {
        const float4* p = (const float4*)(W + (size_t)v * K_DIM + g * 8);
        float4 a = p[0], b = p[1];
        x[0]=a.x; x[1]=a.y; x[2]=a.z; x[3]=a.w; x[4]=b.x; x[5]=b.y; x[6]=b.z; x[7]=b.w;
    } else {
        #pragma unroll
        for (int i = 0; i < 8; i++) x[i] = 0.0f;
    }
    uint32_t hw[4], lw[4];
    split8(x, hw, lw);
    size_t d = ((size_t)v * K_DIM + g * 8) >> 3;
    ((uint4*)g_Wh)[d] = make_uint4(hw[0], hw[1], hw[2], hw[3]);
    ((uint4*)g_Wl)[d] = make_uint4(lw[0], lw[1], lw[2], lw[3]);
}

// prepE: E fp32 [500][1024] -> g_Eh/g_El half [512][1024] (rows >= 500 zero)
__global__ __launch_bounds__(256) void prepE(const float* __restrict__ E) {
    int idx = blockIdx.x * 256 + threadIdx.x;      // 512*128 threads
    int r = idx >> 7, g = idx & 127;
    float x[8];
    if (r < M_ROWS) {
        const float4* p = (const float4*)(E + (size_t)r * K_DIM + g * 8);
        float4 a = p[0], b = p[1];
        x[0]=a.x; x[1]=a.y; x[2]=a.z; x[3]=a.w; x[4]=b.x; x[5]=b.y; x[6]=b.z; x[7]=b.w;
    } else {
        #pragma unroll
        for (int i = 0; i < 8; i++) x[i] = 0.0f;
    }
    uint32_t hw[4], lw[4];
    split8(x, hw, lw);
    size_t d = ((size_t)r * K_DIM + g * 8) >> 3;
    ((uint4*)g_Eh)[d] = make_uint4(hw[0], hw[1], hw[2], hw[3]);
    ((uint4*)g_El)[d] = make_uint4(lw[0], lw[1], lw[2], lw[3]);
}

// ---------------------------------------------------------------------------
// kgemm: HMMA GEMM, fp16 hi/lo 3-product split, pure-cp.async pipeline
// (R5 mainloop — no in-kernel conversion, no extra register pressure).
// Grid (2, NSTRIP): the two M-tiles of a strip are schedule-adjacent so the
// second one's B reads hit L2.
// Epilogue: logits store + fused per-(row, 64col) partial softmax stats.
// Smem/stage: Ah 32K | Al 32K | Bh 16K | Bl 16K = 96K; x2 stages = 192K.
// ---------------------------------------------------------------------------
#define ST_STRIDE 98304
#define AH_OFF 0
#define AL_OFF 32768
#define BH_OFF 65536
#define BL_OFF 81920
#define GEMM_SMEM (2 * ST_STRIDE)

__device__ __forceinline__ void issue_stage(uint32_t sb, int buf, int s,
                                            int m0, int n0, int tid) {
    const int k0 = s * KSTEP;
    uint32_t base = sb + buf * ST_STRIDE;
    // A tiles: 256 rows x 128B (hi+lo)
    #pragma unroll
    for (int i = 0; i < 8; i++) {
        int cid = tid + i * 256;
        int row = cid >> 3, c = cid & 7;
        uint32_t sw = SWZ((uint32_t)(row * 128 + c * 16));
        cpasync16(base + AH_OFF + sw, g_Eh + (size_t)(m0 + row) * K_DIM + k0 + c * 8);
        cpasync16(base + AL_OFF + sw, g_El + (size_t)(m0 + row) * K_DIM + k0 + c * 8);
    }
    // B tiles: 128 rows x 128B (hi+lo); g_Wh/g_Wl padded to N_PAD, no guard
    #pragma unroll
    for (int i = 0; i < 4; i++) {
        int cid = tid + i * 256;
        int row = cid >> 3, c = cid & 7;
        uint32_t sw = SWZ((uint32_t)(row * 128 + c * 16));
        cpasync16(base + BH_OFF + sw, g_Wh + (size_t)(n0 + row) * K_DIM + k0 + c * 8);
        cpasync16(base + BL_OFF + sw, g_Wl + (size_t)(n0 + row) * K_DIM + k0 + c * 8);
    }
}

__global__ __launch_bounds__(256, 1) void kgemm() {
    extern __shared__ char smem[];
    const uint32_t sb = s2u(smem);
    const int tid  = threadIdx.x;
    const int lane = tid & 31;
    const int wid  = tid >> 5;
    const int wm   = (wid >> 1) * 64;   // warp M offset: 0,64,128,192
    const int wn   = (wid & 1) * 64;    // warp N offset: 0,64
    const int m0   = blockIdx.x * CTA_M;   // 2 M-tiles (x is fast -> L2 reuse of B)
    const int n0   = blockIdx.y * CTA_N;   // strip

    float acc[4][8][4];
    #pragma unroll
    for (int i = 0; i < 4; i++)
        #pragma unroll
        for (int j = 0; j < 8; j++)
            #pragma unroll
            for (int q = 0; q < 4; q++) acc[i][j][q] = 0.0f;

    const int arow = wm + (lane & 15);
    const int acol = (lane >> 4) << 4;
    const int brf  = wn + (lane & 7);
    const int bcf  = ((lane >> 3) & 1) << 4;

    issue_stage(sb, 0, 0, m0, n0, tid);
    CP_COMMIT();

    for (int s = 0; s < NSTAGE; s++) {
        const int buf = s & 1;
        if (s + 1 < NSTAGE) {
            issue_stage(sb, buf ^ 1, s + 1, m0, n0, tid);
            CP_COMMIT();
            CP_WAIT(1);
        } else {
            CP_WAIT(0);
        }
        __syncthreads();

        const uint32_t tb = sb + buf * ST_STRIDE;
        #pragma unroll
        for (int kk = 0; kk < 4; kk++) {
            const int kb = kk * 32;
            uint32_t a[4][4], a2[4][4], b[8][2];
            #pragma unroll
            for (int i = 0; i < 4; i++) {
                uint32_t off = (uint32_t)((arow + i * 16) * 128 + kb + acol);
                ldsm_x4(a[i], tb + AH_OFF + SWZ(off));
            }
            #pragma unroll
            for (int j = 0; j < 8; j++) {
                uint32_t off = (uint32_t)((brf + j * 8) * 128 + kb + bcf);
                ldsm_x2(b[j], tb + BH_OFF + SWZ(off));
            }
            #pragma unroll
            for (int i = 0; i < 4; i++)
                #pragma unroll
                for (int j = 0; j < 8; j++) mma16816(acc[i][j], a[i], b[j]);
            #pragma unroll
            for (int i = 0; i < 4; i++) {
                uint32_t off = (uint32_t)((arow + i * 16) * 128 + kb + acol);
                ldsm_x4(a2[i], tb + AL_OFF + SWZ(off));
            }
            #pragma unroll
            for (int i = 0; i < 4; i++)
                #pragma unroll
                for (int j = 0; j < 8; j++) mma16816(acc[i][j], a2[i], b[j]);
            #pragma unroll
            for (int j = 0; j < 8; j++) {
                uint32_t off = (uint32_t)((brf + j * 8) * 128 + kb + bcf);
                ldsm_x2(b[j], tb + BL_OFF + SWZ(off));
            }
            #pragma unroll
            for (int i = 0; i < 4; i++)
                #pragma unroll
                for (int j = 0; j < 8; j++) mma16816(acc[i][j], a[i], b[j]);
        }
        __syncthreads();
    }

    // ---- Epilogue part 1: logits store ----
    const int erow  = m0 + wm + (lane >> 2);
    const int ecol0 = n0 + wn + 2 * (lane & 3);
    #pragma unroll
    for (int i = 0; i < 4; i++) {
        #pragma unroll
        for (int j = 0; j < 8; j++) {
            int cc = ecol0 + j * 8;
            if (cc >= N_COLS) continue;
            int r0 = erow + i * 16;
            if (r0 < M_ROWS)
                *(float2*)(g_logits + (size_t)r0 * N_COLS + cc) =
                    make_float2(acc[i][j][0], acc[i][j][1]);
            int r1 = r0 + 8;
            if (r1 < M_ROWS)
                *(float2*)(g_logits + (size_t)r1 * N_COLS + cc) =
                    make_float2(acc[i][j][2], acc[i][j][3]);
        }
    }

    // ---- Epilogue part 2: partial softmax stats (max, sum-exp per 64 cols) ----
    const int part = blockIdx.y * 2 + (wn >> 6);
    #pragma unroll
    for (int i = 0; i < 4; i++) {
        #pragma unroll
        for (int h = 0; h < 2; h++) {
            int row = m0 + wm + (lane >> 2) + i * 16 + h * 8;
            float mloc = -1e30f;
            #pragma unroll
            for (int j = 0; j < 8; j++) {
                int cc = ecol0 + j * 8;
                if (cc < N_COLS)
                    mloc = fmaxf(mloc, fmaxf(acc[i][j][2*h], acc[i][j][2*h+1]));
            }
            mloc = fmaxf(mloc, __shfl_xor_sync(0xFFFFFFFF, mloc, 1));
            mloc = fmaxf(mloc, __shfl_xor_sync(0xFFFFFFFF, mloc, 2));
            float sloc = 0.0f;
            #pragma unroll
            for (int j = 0; j < 8; j++) {
                int cc = ecol0 + j * 8;
                if (cc < N_COLS)
                    sloc += __expf(acc[i][j][2*h] - mloc) + __expf(acc[i][j][2*h+1] - mloc);
            }
            sloc += __shfl_xor_sync(0xFFFFFFFF, sloc, 1);
            sloc += __shfl_xor_sync(0xFFFFFFFF, sloc, 2);
            if ((lane & 3) == 0) {
                g_pmax[(size_t)row * (2 * NSTRIP) + part] = mloc;
                g_psum[(size_t)row * (2 * NSTRIP) + part] = sloc;
            }
        }
    }
}

// ---------------------------------------------------------------------------
// k2r: merge 782 partials per row -> rowmax, rowsum (with rescale)
// ---------------------------------------------------------------------------
__global__ __launch_bounds__(256) void k2r() {
    const int r = blockIdx.x;
    const float* pm = g_pmax + (size_t)r * (2 * NSTRIP);
    const float* ps = g_psum + (size_t)r * (2 * NSTRIP);
    __shared__ float red[256];
    const int t = threadIdx.x;

    float m = -1e30f;
    for (int i = t; i < 2 * NSTRIP; i += 256) m = fmaxf(m, pm[i]);
    red[t] = m;
    __syncthreads();
    for (int s = 128; s > 0; s >>= 1) {
        if (t < s) red[t] = fmaxf(red[t], red[t + s]);
        __syncthreads();
    }
    m = red[0];
    __syncthreads();

    float sum = 0.0f;
    for (int i = t; i < 2 * NSTRIP; i += 256) sum += ps[i] * __expf(pm[i] - m);
    red[t] = sum;
    __syncthreads();
    for (int s = 128; s > 0; s >>= 1) {
        if (t < s) red[t] += red[t + s];
        __syncthreads();
    }
    if (t == 0) { g_rowmax[r] = m; g_rowsum[r] = red[0]; }
}

// ---------------------------------------------------------------------------
// k2b: c[b,k] = theta[b,k] / S[t_b*50+k]
// ---------------------------------------------------------------------------
__global__ void k2b_coeff(const float* __restrict__ theta) {
    int i = blockIdx.x * 256 + threadIdx.x;
    int b = i / NTOPICS, k = i - b * NTOPICS;
    g_c[i] = theta[i] / g_rowsum[g_tidx[b] * NTOPICS + k];
}

// ---------------------------------------------------------------------------
// k3: out[b,v] = sum_k c[b,k] * exp(L[t_b*50+k, v] - m[.])
// Threads process time-sorted batches -> warp lanes share t -> smem broadcast.
// ---------------------------------------------------------------------------
#define VT  32
#define EBS 34
#define K3_SMEM ((M_ROWS * EBS + M_ROWS) * 4)

__global__ __launch_bounds__(256) void k3_out(float* __restrict__ out) {
    extern __shared__ float sm[];
    float* eb = sm;                   // [500][34]
    float* rm = sm + M_ROWS * EBS;    // [500]
    const int v0  = blockIdx.x * VT;
    const int tid = threadIdx.x;

    for (int r = tid; r < M_ROWS; r += 256) rm[r] = g_rowmax[r];
    __syncthreads();

    for (int i = tid; i < M_ROWS * VT; i += 256) {
        int r = i >> 5, v = i & 31;
        int vc = v0 + v;
        float x = (vc < N_COLS) ? g_logits[(size_t)r * N_COLS + vc] : -1e30f;
        eb[r * EBS + v] = __expf(x - rm[r]);
    }
    __syncthreads();

    const int b  = g_order[tid];
    const int rb = g_tidx[b] * NTOPICS;
    float creg[NTOPICS];
    #pragma unroll
    for (int k = 0; k < NTOPICS; k++) creg[k] = g_c[b * NTOPICS + k];

    float* orow = out + (size_t)b * N_COLS + v0;
    #pragma unroll
    for (int vv = 0; vv < VT; vv += 2) {
        float2 a = make_float2(0.f, 0.f);
        #pragma unroll
        for (int k = 0; k < NTOPICS; k++) {
            float2 e = *(const float2*)&eb[(rb + k) * EBS + vv];
            a.x += creg[k] * e.x;
            a.y += creg[k] * e.y;
        }
        int vc = v0 + vv;
        if (vc + 1 < N_COLS)      *(float2*)(orow + vv) = a;
        else if (vc < N_COLS)     orow[vv] = a.x;
    }
}

// ---------------------------------------------------------------------------
// kernel_launch
// ---------------------------------------------------------------------------
extern "C" void kernel_launch(void* const* d_in, const int* in_sizes, int n_in,
                              void* d_out, int out_size) {
    const float* theta = nullptr;
    const float* W     = nullptr;
    const float* E     = nullptr;
    const int*   tix   = nullptr;
    for (int i = 0; i < n_in; i++) {
        switch (in_sizes[i]) {
            case 12800:    theta = (const float*)d_in[i]; break;
            case 51200000: W     = (const float*)d_in[i]; break;
            case 512000:   E     = (const float*)d_in[i]; break;
            case 256:      tix   = (const int*)d_in[i];   break;
            default: break;
        }
    }
    float* out = (float*)d_out;

    static int attr_set = 0;
    if (!attr_set) {
        cudaFuncSetAttribute(kgemm, cudaFuncAttributeMaxDynamicSharedMemorySize, GEMM_SMEM);
        cudaFuncSetAttribute(k3_out, cudaFuncAttributeMaxDynamicSharedMemorySize, K3_SMEM);
        attr_set = 1;
    }

    k0_index<<<1, 256>>>(tix);
    prepW<<<(N_PAD * 128) / 256, 256>>>(W);
    prepE<<<(M_PAD * 128) / 256, 256>>>(E);

    dim3 gg(M_PAD / CTA_M, NSTRIP);             // (2, 391) — x fast: B L2 reuse
    kgemm<<<gg, 256, GEMM_SMEM>>>();

    k2r<<<M_ROWS, 256>>>();
    k2b_coeff<<<BATCH * NTOPICS / 256, 256>>>(theta);
    k3_out<<<(N_COLS + VT - 1) / VT, 256, K3_SMEM>>>(out);   // 1563 blocks
}